// round 13
// baseline (speedup 1.0000x reference)
#include <cuda_runtime.h>
#include <math.h>

// Problem constants
#define BB    128
#define KTOT  8194             // pos (2) + neg (8192)
#define NMEM  100000
#define TAU_INV 14.2857142857142857f   // 1/0.07
#define KDT_F 3.0f
#define N4    (NMEM * 32)      // float4 per mem = 3,200,000
#define NGRP  2049             // ceil(KTOT/4) groups of 4 k's
#define SPLITS 8
#define COPYB  128
#define GATHB  (BB * SPLITS)   // 1024 gather CTAs
#define TOTB   (COPYB + GATHB) // 1152 (R6 geometry)

// Per-(b,split) partials: [0]=sum e^{v/T}, [1]=sum e^v, [2]=sum e^{v/T}(v-o)
// per array j: 0=cij, 1=cji, 2=intra0, 3=intra1
__device__ float g_part2[BB][SPLITS][12];
// Per-b specials: [a0, c0, a1, c1, ia1, ib1]
__device__ float g_spec[BB][6];
__device__ unsigned int g_ctr = 0;

__device__ __forceinline__ float dot4(float4 a, float4 b) {
    return a.x*b.x + a.y*b.y + a.z*b.z + a.w*b.w;
}

// ---------------------------------------------------------------------------
// Big kernel (exact R6 structure). CTAs [0,COPYB): stream fp32 mems -> out.
// CTAs [COPYB,TOTB): gather, quarter-warp (8 lanes x 16 dims) per k,
// 4 k per warp pass, scalar fp32 dots, exp-sums folded inline (1 MUFU / 4 k).
// Last CTA (atomic counter) does the scalar reduce + momentum update.
// ---------------------------------------------------------------------------
__global__ void __launch_bounds__(256, 4)
big_kernel(const float* __restrict__ emb0,
           const float* __restrict__ emb1,
           const float4* __restrict__ mem0,
           const float4* __restrict__ mem1,
           const int*   __restrict__ pos_idx,
           const int*   __restrict__ neg_idx,
           float* __restrict__ out)
{
    const int bid  = blockIdx.x;
    const int tid  = threadIdx.x;
    const int lane = tid & 31;
    const int warp = tid >> 5;

    if (bid < COPYB) {
        // ---- streaming copy: new_mems baseline ----
        float4* dst = reinterpret_cast<float4*>(out + 4);
        const int stride = COPYB * 256;
        for (int i = bid * 256 + tid; i < N4; i += stride) {
            float4 a = __ldcs(mem0 + i);
            float4 c = __ldcs(mem1 + i);
            __stcs(dst + i,      a);
            __stcs(dst + N4 + i, c);
        }
    } else {
        // ---- gather CTA: one (b, split) per CTA ----
        const int id    = bid - COPYB;
        const int b     = id & (BB - 1);
        const int split = id >> 7;          // 0..SPLITS-1
        const int grp   = lane >> 3;        // quarter-warp: one k each
        const int gl    = lane & 7;
        const int j     = lane & 3;         // accumulator array for this lane

        // emb rows in registers: lane owns float4 slots {gl, gl+8, gl+16, gl+24}
        const float4* e0p = reinterpret_cast<const float4*>(emb0) + b * 32;
        const float4* e1p = reinterpret_cast<const float4*>(emb1) + b * 32;
        float4 e0[4], e1[4];
#pragma unroll
        for (int i = 0; i < 4; i++) { e0[i] = e0p[gl + 8*i]; e1[i] = e1p[gl + 8*i]; }

        float accT = 0.f, acc1 = 0.f, accW = 0.f;

        for (int g = split * 8 + warp; g < NGRP; g += SPLITS * 8) {
            const int  k       = g * 4 + grp;
            const bool v_inter = (k < KTOT);
            int r = 0;
            if (v_inter) r = (k < 2) ? pos_idx[b*2 + k] : neg_idx[b*8192 + (k - 2)];
            const float4* M0 = mem0 + (size_t)r * 32;
            const float4* M1 = mem1 + (size_t)r * 32;

            float s01 = 0.f, s10 = 0.f, si0 = 0.f, si1 = 0.f;
#pragma unroll
            for (int i = 0; i < 4; i++) {
                float4 m0v = M0[gl + 8*i];   // 8 lanes -> one 128B line
                float4 m1v = M1[gl + 8*i];
                s01 += dot4(m0v, e1[i]);     // cij
                s10 += dot4(m1v, e0[i]);     // cji
                si0 += dot4(m0v, e0[i]);     // intra0
                si1 += dot4(m1v, e1[i]);     // intra1
            }
#pragma unroll
            for (int o = 4; o; o >>= 1) {
                s01 += __shfl_xor_sync(0xffffffffu, s01, o);
                s10 += __shfl_xor_sync(0xffffffffu, s10, o);
                si0 += __shfl_xor_sync(0xffffffffu, si0, o);
                si1 += __shfl_xor_sync(0xffffffffu, si1, o);
            }
            const float la  = s01 * TAU_INV;
            const float lc  = s10 * TAU_INV;
            const float lia = si0 * TAU_INV;
            const float lib = si1 * TAU_INV;

            if (g == 0) {                    // split 0, warp 0 only
                if (lane == 0) { g_spec[b][0] = la; g_spec[b][1] = lc; }   // k=0
                if (lane == 8) { g_spec[b][2] = la; g_spec[b][3] = lc;     // k=1
                                 g_spec[b][4] = lia; g_spec[b][5] = lib; }
            }

            // lane's (value, other) pair for its array j
            float v, o;
            if      (j == 0) { v = la;  o = lc;  }
            else if (j == 1) { v = lc;  o = la;  }
            else if (j == 2) { v = lia; o = lib; }
            else             { v = lib; o = lia; }
            const bool valid = (j < 2) ? v_inter : (v_inter && k >= 1);

            const float e3 = valid ? __expf(v * (1.0f/KDT_F)) : 0.f;  // exp(v/3)
            accT += e3;
            acc1 += e3 * e3 * e3;            // exp(v) = exp(v/3)^3
            accW += e3 * (v - o);
        }

        // xor4 folds the gl/gl+4 duplication (exact x2, halved below);
        // xor 8,16 fold the k-quarters.
#pragma unroll
        for (int o = 4; o <= 16; o <<= 1) {
            accT += __shfl_xor_sync(0xffffffffu, accT, o);
            acc1 += __shfl_xor_sync(0xffffffffu, acc1, o);
            accW += __shfl_xor_sync(0xffffffffu, accW, o);
        }

        __shared__ float sred[8][12];
        if (lane < 4) {
            sred[warp][lane*3 + 0] = accT * 0.5f;
            sred[warp][lane*3 + 1] = acc1 * 0.5f;
            sred[warp][lane*3 + 2] = accW * 0.5f;
        }
        __syncthreads();
        if (tid < 12) {
            float s = 0.f;
            for (int w = 0; w < 8; w++) s += sred[w][tid];   // fixed order
            g_part2[b][split][tid] = s;
        }
    }

    // ======================= fused finalize tail =======================
    __shared__ bool s_last;
    __syncthreads();
    if (tid == 0) {
        __threadfence();
        unsigned old = atomicAdd(&g_ctr, 1u);
        s_last = (old == TOTB - 1);
    }
    __syncthreads();
    if (!s_last) return;
    __threadfence();

    // ---- scalar reduce (threads 0..127) ----
    {
        float raw[4] = {0.f, 0.f, 0.f, 0.f};
        if (tid < BB) {
            float s2[12];
#pragma unroll
            for (int q = 0; q < 12; q++) {
                float a = 0.f;
                for (int sp = 0; sp < SPLITS; sp++) a += g_part2[tid][sp][q];
                s2[q] = a;
            }
            const float sAT = s2[0],  sA  = s2[1],  w1 = s2[2];
            const float sBT = s2[3],  sB  = s2[4],  w0 = s2[5];
            const float sIaT= s2[6],  sIa = s2[7],  w3 = s2[8];
            const float sIbT= s2[9],  sIb = s2[10], w2 = s2[11];
            const float LA  = logf(sA),  LB  = logf(sB);
            const float LIa = logf(sIa), LIb = logf(sIb);
            const float a0 = g_spec[tid][0], c0 = g_spec[tid][1];
            const float a1 = g_spec[tid][2], c1 = g_spec[tid][3];
            const float ia1 = g_spec[tid][4], ib1 = g_spec[tid][5];
            raw[0] = -(ia1 - LIa) - (ib1 - LIb);                     // vcl
            raw[1] = KDT_F * (w2 / sIbT + w3 / sIaT);                // soft_vcl
            raw[2] = -(0.5f*(a0+a1) - LA) - (0.5f*(c0+c1) - LB);     // icl
            raw[3] = KDT_F * (w0 / sBT + w1 / sAT);                  // soft_icl
        }
        __shared__ float scr[8][4];
#pragma unroll
        for (int q = 0; q < 4; q++) {
            float v = raw[q];
#pragma unroll
            for (int o = 16; o; o >>= 1) v += __shfl_xor_sync(0xffffffffu, v, o);
            if (lane == 0) scr[warp][q] = v;
        }
        __syncthreads();
        if (tid == 0) {
#pragma unroll
            for (int q = 0; q < 4; q++) {
                float v = 0.f;
                for (int w = 0; w < 8; w++) v += scr[w][q];
                out[q] = v / (float)BB;
            }
        }
    }

    // ---- momentum update: 256 warp-tasks (b, net), last-wins dedup ----
    for (int task = warp; task < 256; task += 8) {
        const int bb  = task & (BB - 1);
        const int net = task >> 7;
        const int r   = pos_idx[bb * 2];
        bool owner = true;
        for (int bp = bb + 1; bp < BB; bp++)
            if (pos_idx[bp * 2] == r) { owner = false; break; }
        if (!owner) continue;

        const float4* mem  = net ? mem1 : mem0;
        const float4* embp = reinterpret_cast<const float4*>(net ? emb1 : emb0);
        float4* dst = reinterpret_cast<float4*>(out + 4) + (size_t)net * N4;

        float4 m = mem[(size_t)r * 32 + lane];
        float4 e = embp[bb * 32 + lane];
        float4 u;
        u.x = 0.5f * (m.x + e.x);   // MOM = 0.5
        u.y = 0.5f * (m.y + e.y);
        u.z = 0.5f * (m.z + e.z);
        u.w = 0.5f * (m.w + e.w);
        float s2 = u.x*u.x + u.y*u.y + u.z*u.z + u.w*u.w;
#pragma unroll
        for (int o = 16; o; o >>= 1) s2 += __shfl_xor_sync(0xffffffffu, s2, o);
        const float inv = 1.0f / sqrtf(s2);
        u.x *= inv; u.y *= inv; u.z *= inv; u.w *= inv;
        dst[(size_t)r * 32 + lane] = u;
    }

    if (tid == 0) g_ctr = 0;   // reset for next graph replay
}

// ---------------------------------------------------------------------------
extern "C" void kernel_launch(void* const* d_in, const int* in_sizes, int n_in,
                              void* d_out, int out_size)
{
    const float* emb0    = (const float*)d_in[0];
    const float* emb1    = (const float*)d_in[1];
    const float* mem0    = (const float*)d_in[2];
    const float* mem1    = (const float*)d_in[3];
    const int*   pos_idx = (const int*)  d_in[4];
    const int*   neg_idx = (const int*)  d_in[5];
    float* out = (float*)d_out;

    // out layout: [vcl, soft_vcl, icl, soft_icl, new_mem0, new_mem1]
    big_kernel<<<TOTB, 256>>>(emb0, emb1,
                              (const float4*)mem0, (const float4*)mem1,
                              pos_idx, neg_idx, out);
}

// round 14
// speedup vs baseline: 1.7419x; 1.7419x over previous
#include <cuda_runtime.h>
#include <math.h>

// Problem constants
#define BB    128
#define DD    128
#define KTOT  8194            // pos (2) + neg (8192)
#define NMEM  100000
#define TAU_INV 14.2857142857142857f   // 1/0.07
#define KDT_F 3.0f
#define N4    (NMEM * (DD/4)) // float4 per mem = 3,200,000
#define NGRP  ((KTOT + 3) / 4)         // 2049 k-groups of 4
#define SPLITS 8
#define COPYB  128            // copy CTAs (prefix of the big grid)

// Per-(b,split) partial sums, 12 each:
// j*3+0 = sum exp(v/T), j*3+1 = sum exp(v), j*3+2 = sum exp(v/T)*(v - other)
// j: 0=cij, 1=cji, 2=intra0, 3=intra1
__device__ float g_part2[BB][SPLITS][12];
// Per-b specials: [a0, c0, a1, c1, ia1, ib1] (logits at k=0,1)
__device__ float g_spec[BB][6];

__device__ __forceinline__ float dot4(float4 a, float4 b) {
    return a.x*b.x + a.y*b.y + a.z*b.z + a.w*b.w;
}

// ---------------------------------------------------------------------------
// Big kernel: CTAs [0,COPYB) stream-copy mem0/mem1 into out (DRAM-bound),
// CTAs [COPYB, COPYB+128*SPLITS) gather + compute all exp-sums inline
// (L2-bound; MUFU hidden under LDG latency). The two classes of CTAs run
// concurrently on the same SMs, overlapping DRAM and L2 bandwidth.
// ---------------------------------------------------------------------------
__global__ void __launch_bounds__(256, 4)
big_kernel(const float* __restrict__ emb0,
           const float* __restrict__ emb1,
           const float4* __restrict__ mem0,
           const float4* __restrict__ mem1,
           const int*   __restrict__ pos_idx,
           const int*   __restrict__ neg_idx,
           float* __restrict__ out)
{
    const int bid = blockIdx.x;

    if (bid < COPYB) {
        // ---- streaming copy: new_mems baseline ----
        float4* dst = reinterpret_cast<float4*>(out + 4);
        const int stride = COPYB * 256;
        for (int i = bid * 256 + threadIdx.x; i < N4; i += stride) {
            float4 a = mem0[i];
            float4 c = mem1[i];
            __stcs(dst + i,      a);   // evict-first: don't pollute L2
            __stcs(dst + N4 + i, c);
        }
        return;
    }

    // ---- gather CTA ----
    const int id    = bid - COPYB;
    const int b     = id & (BB - 1);
    const int split = id >> 7;           // 0..SPLITS-1

    const int tid  = threadIdx.x;
    const int lane = tid & 31;
    const int warp = tid >> 5;           // 0..7
    const int grp  = lane >> 3;          // quarter-warp: one k each
    const int gl   = lane & 7;
    const int j    = lane & 3;           // array this lane accumulates

    // emb rows in registers: lane owns float4 slots {gl, gl+8, gl+16, gl+24}
    const float4* e0p = reinterpret_cast<const float4*>(emb0) + b * 32;
    const float4* e1p = reinterpret_cast<const float4*>(emb1) + b * 32;
    float4 e0[4], e1[4];
#pragma unroll
    for (int i = 0; i < 4; i++) { e0[i] = e0p[gl + 8*i]; e1[i] = e1p[gl + 8*i]; }

    float accT = 0.f, acc1 = 0.f, accW = 0.f;

    for (int g = split * 8 + warp; g < NGRP; g += SPLITS * 8) {
        const int  k       = g * 4 + grp;
        const bool v_inter = (k < KTOT);
        int r = 0;
        if (v_inter) r = (k < 2) ? pos_idx[b*2 + k] : neg_idx[b*8192 + (k - 2)];
        const float4* M0 = mem0 + (size_t)r * 32;
        const float4* M1 = mem1 + (size_t)r * 32;

        float s01 = 0.f, s10 = 0.f, si0 = 0.f, si1 = 0.f;
#pragma unroll
        for (int i = 0; i < 4; i++) {
            float4 m0v = M0[gl + 8*i];   // 8 lanes -> one 128B line
            float4 m1v = M1[gl + 8*i];
            s01 += dot4(m0v, e1[i]);     // cij
            s10 += dot4(m1v, e0[i]);     // cji
            si0 += dot4(m0v, e0[i]);     // intra0
            si1 += dot4(m1v, e1[i]);     // intra1
        }
#pragma unroll
        for (int o = 4; o; o >>= 1) {
            s01 += __shfl_xor_sync(0xffffffffu, s01, o);
            s10 += __shfl_xor_sync(0xffffffffu, s10, o);
            si0 += __shfl_xor_sync(0xffffffffu, si0, o);
            si1 += __shfl_xor_sync(0xffffffffu, si1, o);
        }
        const float la  = s01 * TAU_INV;
        const float lc  = s10 * TAU_INV;
        const float lia = si0 * TAU_INV;
        const float lib = si1 * TAU_INV;

        if (g == 0) {                    // split 0, warp 0 only
            if (lane == 0) { g_spec[b][0] = la; g_spec[b][1] = lc; }   // k=0
            if (lane == 8) { g_spec[b][2] = la; g_spec[b][3] = lc;     // k=1
                             g_spec[b][4] = lia; g_spec[b][5] = lib; }
        }

        // lane's (value, other) pair for its array
        float v, o;
        if      (j == 0) { v = la;  o = lc;  }
        else if (j == 1) { v = lc;  o = la;  }
        else if (j == 2) { v = lia; o = lib; }
        else             { v = lib; o = lia; }
        const bool valid = (j < 2) ? v_inter : (v_inter && k >= 1);

        float e3 = valid ? __expf(v * (1.0f / KDT_F)) : 0.f;  // exp(v/3)
        accT += e3;
        acc1 += e3 * e3 * e3;            // exp(v) = exp(v/3)^3
        accW += e3 * (v - o);
    }

    // reduce lanes with equal (lane & 3): xor 4 folds the gl/gl+4 duplication
    // (exact x2, halved below); xor 8,16 fold the k-quarters.
#pragma unroll
    for (int o = 4; o <= 16; o <<= 1) {
        accT += __shfl_xor_sync(0xffffffffu, accT, o);
        acc1 += __shfl_xor_sync(0xffffffffu, acc1, o);
        accW += __shfl_xor_sync(0xffffffffu, accW, o);
    }

    __shared__ float sred[8][12];
    if (lane < 4) {
        sred[warp][lane*3 + 0] = accT * 0.5f;
        sred[warp][lane*3 + 1] = acc1 * 0.5f;
        sred[warp][lane*3 + 2] = accW * 0.5f;
    }
    __syncthreads();
    if (tid < 12) {
        float s = 0.f;
        for (int w = 0; w < 8; w++) s += sred[w][tid];   // fixed order
        g_part2[b][split][tid] = s;
    }
}

// ---------------------------------------------------------------------------
// Finalize: CTA 0 reduces partials into the 4 scalars; CTAs 1..32 apply the
// momentum update to the p0 rows of the output copies (last-wins dedup).
// ---------------------------------------------------------------------------
__global__ void __launch_bounds__(256)
finalize_kernel(const float* __restrict__ emb0,
                const float* __restrict__ emb1,
                const float4* __restrict__ mem0,
                const float4* __restrict__ mem1,
                const int*   __restrict__ pos_idx,
                float* __restrict__ out)
{
    if (blockIdx.x == 0) {
        const int t = threadIdx.x;
        float raw[4] = {0.f, 0.f, 0.f, 0.f};
        if (t < BB) {
            float s[12];
#pragma unroll
            for (int q = 0; q < 12; q++) {
                float acc = 0.f;
                for (int sp = 0; sp < SPLITS; sp++) acc += g_part2[t][sp][q];
                s[q] = acc;
            }
            const float sAT = s[0],  sA  = s[1],  w1 = s[2];
            const float sBT = s[3],  sB  = s[4],  w0 = s[5];
            const float sIaT= s[6],  sIa = s[7],  w3 = s[8];
            const float sIbT= s[9],  sIb = s[10], w2 = s[11];
            const float LA  = logf(sA),  LB  = logf(sB);
            const float LIa = logf(sIa), LIb = logf(sIb);
            const float a0 = g_spec[t][0], c0 = g_spec[t][1];
            const float a1 = g_spec[t][2], c1 = g_spec[t][3];
            const float ia1 = g_spec[t][4], ib1 = g_spec[t][5];
            raw[0] = -(ia1 - LIa) - (ib1 - LIb);                       // vcl
            raw[1] = KDT_F * (w2 / sIbT + w3 / sIaT);                  // soft_vcl
            raw[2] = -(0.5f*(a0+a1) - LA) - (0.5f*(c0+c1) - LB);       // icl
            raw[3] = KDT_F * (w0 / sBT + w1 / sAT);                    // soft_icl
        }
        __shared__ float scr[8][4];
#pragma unroll
        for (int q = 0; q < 4; q++) {
            float v = raw[q];
#pragma unroll
            for (int o = 16; o; o >>= 1) v += __shfl_xor_sync(0xffffffffu, v, o);
            if ((t & 31) == 0) scr[t >> 5][q] = v;
        }
        __syncthreads();
        if (t == 0) {
#pragma unroll
            for (int q = 0; q < 4; q++) {
                float v = 0.f;
                for (int w = 0; w < 8; w++) v += scr[w][q];
                out[q] = v / (float)BB;
            }
        }
        return;
    }

    // ---- momentum update: 256 warp tasks = (b, net) ----
    const int w    = (blockIdx.x - 1) * 8 + (threadIdx.x >> 5);  // 0..255
    const int lane = threadIdx.x & 31;
    const int b    = w & (BB - 1);
    const int net  = w >> 7;
    const int r    = pos_idx[b * 2];
    for (int bp = b + 1; bp < BB; bp++)
        if (pos_idx[bp * 2] == r) return;        // a later b overwrites

    const float4* mem  = net ? mem1 : mem0;
    const float4* embp = reinterpret_cast<const float4*>(net ? emb1 : emb0);
    float4* dst = reinterpret_cast<float4*>(out + 4) + (size_t)net * N4;

    float4 m = mem[(size_t)r * 32 + lane];
    float4 e = embp[b * 32 + lane];
    float4 u;
    u.x = 0.5f * (m.x + e.x);    // MOM = 0.5
    u.y = 0.5f * (m.y + e.y);
    u.z = 0.5f * (m.z + e.z);
    u.w = 0.5f * (m.w + e.w);
    float s2 = u.x*u.x + u.y*u.y + u.z*u.z + u.w*u.w;
#pragma unroll
    for (int o = 16; o; o >>= 1) s2 += __shfl_xor_sync(0xffffffffu, s2, o);
    const float inv = 1.0f / sqrtf(s2);
    u.x *= inv; u.y *= inv; u.z *= inv; u.w *= inv;
    dst[(size_t)r * 32 + lane] = u;
}

// ---------------------------------------------------------------------------
extern "C" void kernel_launch(void* const* d_in, const int* in_sizes, int n_in,
                              void* d_out, int out_size)
{
    const float* emb0    = (const float*)d_in[0];
    const float* emb1    = (const float*)d_in[1];
    const float* mem0    = (const float*)d_in[2];
    const float* mem1    = (const float*)d_in[3];
    const int*   pos_idx = (const int*)  d_in[4];
    const int*   neg_idx = (const int*)  d_in[5];
    float* out = (float*)d_out;

    // out layout: [vcl, soft_vcl, icl, soft_icl, new_mem0, new_mem1]
    big_kernel<<<COPYB + BB * SPLITS, 256>>>(emb0, emb1,
                                             (const float4*)mem0,
                                             (const float4*)mem1,
                                             pos_idx, neg_idx, out);
    finalize_kernel<<<33, 256>>>(emb0, emb1,
                                 (const float4*)mem0, (const float4*)mem1,
                                 pos_idx, out);
}

// round 15
// speedup vs baseline: 2.3590x; 1.3543x over previous
#include <cuda_runtime.h>
#include <cuda_bf16.h>
#include <math.h>

// Problem constants
#define BB    128
#define KTOT  8194             // pos (2) + neg (8192)
#define NMEM  100000
#define TAU_INV 14.2857142857142857f   // 1/0.07
#define KDT_F 3.0f
#define N4    (NMEM * 32)      // float4 per mem = 3,200,000
#define SPLITS 8
#define GATHB (BB * SPLITS)    // 1024 gather CTAs
#define NG8   ((KTOT + 7) / 8) // 1025 groups of 8 k's

// bf16 mirror, row-interleaved: row r = [mem0 r: 16 uint4][mem1 r: 16 uint4]
__device__ uint4 g_membf[NMEM * 32];

// Per-(b,split) partials: j*3+0 = sum e^{v/T}, +1 = sum e^v, +2 = sum e^{v/T}(v-o)
// j: 0=cij, 1=cji, 2=intra0, 3=intra1
__device__ float g_part2[BB][SPLITS][12];
// Per-b specials: [a0, c0, a1, c1, ia1, ib1]
__device__ float g_spec[BB][6];

// ---------------------------------------------------------------------------
// Prep: one streaming pass over fp32 mems -> fp32 copy in out (L2-bypass) +
// bf16 mirror (normal stores -> L2-resident). One task per thread.
// ---------------------------------------------------------------------------
__global__ void __launch_bounds__(256)
prep_kernel(const float4* __restrict__ m0, const float4* __restrict__ m1,
            float4* __restrict__ dst)   // = out + 4
{
    const int u = blockIdx.x * blockDim.x + threadIdx.x;   // [0, NMEM*16)
    if (u >= NMEM * 16) return;
    const int r = u >> 4, s = u & 15;
    const size_t i0 = (size_t)r * 32 + s * 2;

    float4 a0 = __ldcs(m0 + i0), a1 = __ldcs(m0 + i0 + 1);
    float4 c0 = __ldcs(m1 + i0), c1 = __ldcs(m1 + i0 + 1);
    __stcs(dst + i0,          a0);
    __stcs(dst + i0 + 1,      a1);
    __stcs(dst + N4 + i0,     c0);
    __stcs(dst + N4 + i0 + 1, c1);

    union { uint4 u4; __nv_bfloat162 h[4]; } p;
    p.h[0] = __float22bfloat162_rn(make_float2(a0.x, a0.y));
    p.h[1] = __float22bfloat162_rn(make_float2(a0.z, a0.w));
    p.h[2] = __float22bfloat162_rn(make_float2(a1.x, a1.y));
    p.h[3] = __float22bfloat162_rn(make_float2(a1.z, a1.w));
    g_membf[(size_t)r * 32 + s] = p.u4;
    p.h[0] = __float22bfloat162_rn(make_float2(c0.x, c0.y));
    p.h[1] = __float22bfloat162_rn(make_float2(c0.z, c0.w));
    p.h[2] = __float22bfloat162_rn(make_float2(c1.x, c1.y));
    p.h[3] = __float22bfloat162_rn(make_float2(c1.z, c1.w));
    g_membf[(size_t)r * 32 + 16 + s] = p.u4;
}

// 8 bf16 (one uint4) dotted against two fp32 emb fragments
__device__ __forceinline__ void dot8(uint4 q,
                                     float4 ej0, float4 ej1,
                                     float4 ek0, float4 ek1,
                                     float& sj, float& sk)
{
    __nv_bfloat162* h = reinterpret_cast<__nv_bfloat162*>(&q);
    float2 f0 = __bfloat1622float2(h[0]);
    float2 f1 = __bfloat1622float2(h[1]);
    float2 f2 = __bfloat1622float2(h[2]);
    float2 f3 = __bfloat1622float2(h[3]);
    sj += f0.x*ej0.x + f0.y*ej0.y + f1.x*ej0.z + f1.y*ej0.w
        + f2.x*ej1.x + f2.y*ej1.y + f3.x*ej1.z + f3.y*ej1.w;
    sk += f0.x*ek0.x + f0.y*ek0.y + f1.x*ek0.z + f1.y*ek0.w
        + f2.x*ek1.x + f2.y*ek1.y + f3.x*ek1.z + f3.y*ek1.w;
}

// ---------------------------------------------------------------------------
// Gather: quarter-warp per k, 2 k's unrolled (8 LDG.128/lane in flight),
// reading the L2-resident bf16 mirror. All exp-sums folded inline.
// (Exact R8 structure, tail removed.)
// ---------------------------------------------------------------------------
__global__ void __launch_bounds__(256, 3)
gather_kernel(const float* __restrict__ emb0,
              const float* __restrict__ emb1,
              const int*   __restrict__ pos_idx,
              const int*   __restrict__ neg_idx)
{
    const int tid  = threadIdx.x;
    const int lane = tid & 31;
    const int warp = tid >> 5;            // 0..7
    const int b     = blockIdx.x & (BB - 1);
    const int split = blockIdx.x >> 7;    // 0..SPLITS-1
    const int grp   = lane >> 3;          // quarter-warp: one k each
    const int gl    = lane & 7;
    const int j     = lane & 3;           // accumulator array for this lane

    // emb fragments: lane covers dims [(i*8+gl)*8, +8) for i in {0,1}
    const float4* e0p = reinterpret_cast<const float4*>(emb0) + b * 32;
    const float4* e1p = reinterpret_cast<const float4*>(emb1) + b * 32;
    float4 e0r[2][2], e1r[2][2];
#pragma unroll
    for (int i = 0; i < 2; i++)
#pragma unroll
        for (int q = 0; q < 2; q++) {
            e0r[i][q] = e0p[(i*8 + gl)*2 + q];
            e1r[i][q] = e1p[(i*8 + gl)*2 + q];
        }

    float accT = 0.f, acc1 = 0.f, accW = 0.f;

    for (int gg = split * 8 + warp; gg < NG8; gg += SPLITS * 8) {
        const int kb = gg * 8;
        const int k0 = kb + grp;          // first 4-k group
        const int k1 = kb + 4 + grp;      // second 4-k group
        const bool v0 = (k0 < KTOT), v1 = (k1 < KTOT);
        int r0 = 0, r1 = 0;
        if (v0) r0 = (k0 < 2) ? pos_idx[b*2 + k0] : neg_idx[b*8192 + (k0 - 2)];
        if (v1) r1 = (k1 < 2) ? pos_idx[b*2 + k1] : neg_idx[b*8192 + (k1 - 2)];
        const uint4* R0 = g_membf + (size_t)r0 * 32;
        const uint4* R1 = g_membf + (size_t)r1 * 32;

        // 8 independent 16B loads (quarter-warp => 128B lines)
        uint4 q0 = R0[gl],      q1 = R0[8 + gl];
        uint4 q2 = R0[16 + gl], q3 = R0[24 + gl];
        uint4 q4 = R1[gl],      q5 = R1[8 + gl];
        uint4 q6 = R1[16 + gl], q7 = R1[24 + gl];

        float s[8] = {0.f,0.f,0.f,0.f,0.f,0.f,0.f,0.f};
        // group 0: s[0]=cij, s[1]=cji, s[2]=intra0, s[3]=intra1
        dot8(q0, e1r[0][0], e1r[0][1], e0r[0][0], e0r[0][1], s[0], s[2]);
        dot8(q1, e1r[1][0], e1r[1][1], e0r[1][0], e0r[1][1], s[0], s[2]);
        dot8(q2, e0r[0][0], e0r[0][1], e1r[0][0], e1r[0][1], s[1], s[3]);
        dot8(q3, e0r[1][0], e0r[1][1], e1r[1][0], e1r[1][1], s[1], s[3]);
        // group 1
        dot8(q4, e1r[0][0], e1r[0][1], e0r[0][0], e0r[0][1], s[4], s[6]);
        dot8(q5, e1r[1][0], e1r[1][1], e0r[1][0], e0r[1][1], s[4], s[6]);
        dot8(q6, e0r[0][0], e0r[0][1], e1r[0][0], e1r[0][1], s[5], s[7]);
        dot8(q7, e0r[1][0], e0r[1][1], e1r[1][0], e1r[1][1], s[5], s[7]);

        // interleaved quarter-warp reduce of all 8 sums
#pragma unroll
        for (int o = 4; o; o >>= 1)
#pragma unroll
            for (int qq = 0; qq < 8; qq++)
                s[qq] += __shfl_xor_sync(0xffffffffu, s[qq], o);

        const float la0  = s[0]*TAU_INV, lc0  = s[1]*TAU_INV;
        const float lia0 = s[2]*TAU_INV, lib0 = s[3]*TAU_INV;
        const float la1  = s[4]*TAU_INV, lc1  = s[5]*TAU_INV;
        const float lia1 = s[6]*TAU_INV, lib1 = s[7]*TAU_INV;

        if (gg == 0) {                    // split 0, warp 0, first iter
            if (lane == 0) { g_spec[b][0] = la0; g_spec[b][1] = lc0; }  // k=0
            if (lane == 8) { g_spec[b][2] = la0; g_spec[b][3] = lc0;    // k=1
                             g_spec[b][4] = lia0; g_spec[b][5] = lib0; }
        }

        float v0v, o0v, v1v, o1v;
        if      (j == 0) { v0v = la0;  o0v = lc0;  v1v = la1;  o1v = lc1;  }
        else if (j == 1) { v0v = lc0;  o0v = la0;  v1v = lc1;  o1v = la1;  }
        else if (j == 2) { v0v = lia0; o0v = lib0; v1v = lia1; o1v = lib1; }
        else             { v0v = lib0; o0v = lia0; v1v = lib1; o1v = lia1; }
        const bool val0 = (j < 2) ? v0 : (v0 && k0 >= 1);  // intra excludes k=0
        const bool val1 = v1;                              // k1 >= 4 always

        const float e30 = val0 ? __expf(v0v * (1.0f/KDT_F)) : 0.f;
        const float e31 = val1 ? __expf(v1v * (1.0f/KDT_F)) : 0.f;
        accT += e30 + e31;
        acc1 += e30*e30*e30 + e31*e31*e31;   // exp(v) = exp(v/3)^3
        accW += e30*(v0v - o0v) + e31*(v1v - o1v);
    }

    // xor4 folds the gl/gl+4 duplication (exact x2, halved below);
    // xor 8,16 fold the k-quarters.
#pragma unroll
    for (int o = 4; o <= 16; o <<= 1) {
        accT += __shfl_xor_sync(0xffffffffu, accT, o);
        acc1 += __shfl_xor_sync(0xffffffffu, acc1, o);
        accW += __shfl_xor_sync(0xffffffffu, accW, o);
    }

    __shared__ float sred[8][12];
    if (lane < 4) {
        sred[warp][lane*3 + 0] = accT * 0.5f;
        sred[warp][lane*3 + 1] = acc1 * 0.5f;
        sred[warp][lane*3 + 2] = accW * 0.5f;
    }
    __syncthreads();
    if (tid < 12) {
        float sum = 0.f;
        for (int w = 0; w < 8; w++) sum += sred[w][tid];   // fixed order
        g_part2[b][split][tid] = sum;
    }
}

// ---------------------------------------------------------------------------
// Finalize: CTA 0 reduces partials into the 4 scalars; CTAs 1..32 apply the
// momentum update (p0 values staged in SMEM for the last-wins dedup scan).
// ---------------------------------------------------------------------------
__global__ void __launch_bounds__(256)
finalize_kernel(const float* __restrict__ emb0,
                const float* __restrict__ emb1,
                const float4* __restrict__ mem0,
                const float4* __restrict__ mem1,
                const int*   __restrict__ pos_idx,
                float* __restrict__ out)
{
    if (blockIdx.x == 0) {
        const int t = threadIdx.x;
        float raw[4] = {0.f, 0.f, 0.f, 0.f};
        if (t < BB) {
            float s[12];
#pragma unroll
            for (int q = 0; q < 12; q++) {
                float acc = 0.f;
                for (int sp = 0; sp < SPLITS; sp++) acc += g_part2[t][sp][q];
                s[q] = acc;
            }
            const float sAT = s[0],  sA  = s[1],  w1 = s[2];
            const float sBT = s[3],  sB  = s[4],  w0 = s[5];
            const float sIaT= s[6],  sIa = s[7],  w3 = s[8];
            const float sIbT= s[9],  sIb = s[10], w2 = s[11];
            const float LA  = logf(sA),  LB  = logf(sB);
            const float LIa = logf(sIa), LIb = logf(sIb);
            const float a0 = g_spec[t][0], c0 = g_spec[t][1];
            const float a1 = g_spec[t][2], c1 = g_spec[t][3];
            const float ia1 = g_spec[t][4], ib1 = g_spec[t][5];
            raw[0] = -(ia1 - LIa) - (ib1 - LIb);                       // vcl
            raw[1] = KDT_F * (w2 / sIbT + w3 / sIaT);                  // soft_vcl
            raw[2] = -(0.5f*(a0+a1) - LA) - (0.5f*(c0+c1) - LB);       // icl
            raw[3] = KDT_F * (w0 / sBT + w1 / sAT);                    // soft_icl
        }
        __shared__ float scr[8][4];
#pragma unroll
        for (int q = 0; q < 4; q++) {
            float v = raw[q];
#pragma unroll
            for (int o = 16; o; o >>= 1) v += __shfl_xor_sync(0xffffffffu, v, o);
            if ((t & 31) == 0) scr[t >> 5][q] = v;
        }
        __syncthreads();
        if (t == 0) {
#pragma unroll
            for (int q = 0; q < 4; q++) {
                float v = 0.f;
                for (int w = 0; w < 8; w++) v += scr[w][q];
                out[q] = v / (float)BB;
            }
        }
        return;
    }

    // ---- momentum update: 256 warp tasks = (b, net), p0 staged in SMEM ----
    __shared__ int sp0[BB];
    for (int i = threadIdx.x; i < BB; i += 256) sp0[i] = pos_idx[i * 2];
    __syncthreads();

    const int w    = (blockIdx.x - 1) * 8 + (threadIdx.x >> 5);  // 0..255
    const int lane = threadIdx.x & 31;
    const int b    = w & (BB - 1);
    const int net  = w >> 7;
    const int r    = sp0[b];
    for (int bp = b + 1; bp < BB; bp++)
        if (sp0[bp] == r) return;        // a later b overwrites (last-wins)

    const float4* mem  = net ? mem1 : mem0;
    const float4* embp = reinterpret_cast<const float4*>(net ? emb1 : emb0);
    float4* dst = reinterpret_cast<float4*>(out + 4) + (size_t)net * N4;

    float4 m = mem[(size_t)r * 32 + lane];
    float4 e = embp[b * 32 + lane];
    float4 u;
    u.x = 0.5f * (m.x + e.x);    // MOM = 0.5
    u.y = 0.5f * (m.y + e.y);
    u.z = 0.5f * (m.z + e.z);
    u.w = 0.5f * (m.w + e.w);
    float s2 = u.x*u.x + u.y*u.y + u.z*u.z + u.w*u.w;
#pragma unroll
    for (int o = 16; o; o >>= 1) s2 += __shfl_xor_sync(0xffffffffu, s2, o);
    const float inv = 1.0f / sqrtf(s2);
    u.x *= inv; u.y *= inv; u.z *= inv; u.w *= inv;
    dst[(size_t)r * 32 + lane] = u;
}

// ---------------------------------------------------------------------------
extern "C" void kernel_launch(void* const* d_in, const int* in_sizes, int n_in,
                              void* d_out, int out_size)
{
    const float* emb0    = (const float*)d_in[0];
    const float* emb1    = (const float*)d_in[1];
    const float* mem0    = (const float*)d_in[2];
    const float* mem1    = (const float*)d_in[3];
    const int*   pos_idx = (const int*)  d_in[4];
    const int*   neg_idx = (const int*)  d_in[5];
    float* out = (float*)d_out;

    // out layout: [vcl, soft_vcl, icl, soft_icl, new_mem0, new_mem1]
    prep_kernel<<<(NMEM*16 + 255)/256, 256>>>((const float4*)mem0,
                                              (const float4*)mem1,
                                              (float4*)(out + 4));
    gather_kernel<<<GATHB, 256>>>(emb0, emb1, pos_idx, neg_idx);
    finalize_kernel<<<33, 256>>>(emb0, emb1,
                                 (const float4*)mem0, (const float4*)mem1,
                                 pos_idx, out);
}